// round 3
// baseline (speedup 1.0000x reference)
#include <cuda_runtime.h>

// Problem dims (fixed by reference setup_inputs)
#define BB   64      // batch
#define NN   1024    // capsules in
#define EE   8       // capsules out
#define OO   32      // out_dim
#define II   64      // in_dim
#define EO   256     // EE*OO
#define NEO  (NN*EO) // per-batch u_hat stride = 262144

// ---------------------------------------------------------------------------
// Scratch (device globals; no allocation allowed)
// ---------------------------------------------------------------------------
__device__ float g_u_hat[(size_t)BB * NN * EO];   // 64 MB   [b][n][eo]
__device__ float g_spart[8 * BB * EO];            // 512 KB  [chunk][b][eo]
__device__ float g_v[BB * EO];                    // v from squash
__device__ float g_b[BB * NN * EE];               // routing logits [b][n][e]

// ---------------------------------------------------------------------------
// fp32x2 packed helpers (PTX-only; ptxas never auto-fuses FFMA2)
// ---------------------------------------------------------------------------
__device__ __forceinline__ void ffma2(unsigned long long& d,
                                      unsigned long long a,
                                      unsigned long long b) {
    asm("fma.rn.f32x2 %0, %1, %2, %0;" : "+l"(d) : "l"(a), "l"(b));
}
__device__ __forceinline__ unsigned long long dup2(float x) {
    unsigned long long r;
    asm("mov.b64 %0, {%1, %1};" : "=l"(r) : "f"(x));
    return r;
}
__device__ __forceinline__ float2 asf2(unsigned long long v) {
    union { unsigned long long u; float2 f; } c; c.u = v; return c.f;
}

// ---------------------------------------------------------------------------
// Kernel 1: u_hat[b,n,eo] = sum_i W[n,eo,i] * u[b,n,i]
// One CTA per n. 256 threads. Per thread: 8 b-rows x 8 eo-cols via f32x2.
// SMEM: sW [k][eo] XOR-swizzled (fill AND read conflict-free), sU [k][b] pad 66.
// ---------------------------------------------------------------------------
#define GEMM_SMEM_FLOATS (64*256 + 64*66)
#define GEMM_SMEM_BYTES  (GEMM_SMEM_FLOATS * 4)

__global__ __launch_bounds__(256, 2)
void gemm_kernel(const float* __restrict__ u, const float* __restrict__ W) {
    extern __shared__ float smem[];
    float* sW = smem;            // [64][256] swizzled
    float* sU = smem + 64 * 256; // [64][66]

    const int n = blockIdx.x;
    const int t = threadIdx.x;
    const int w = t >> 5;
    const int l = t & 31;

    // ---- fill sU: sU[k][b] = u[b][n][k] (coalesced global, 2-way STS)
    {
        const float* ug = u + n * II;
        #pragma unroll
        for (int it = 0; it < 16; ++it) {
            int idx = t + it * 256;           // 0..4095
            int b = idx >> 6, k = idx & 63;
            sU[k * 66 + b] = ug[(size_t)b * (NN * II) + k];
        }
    }
    // ---- fill sW swizzled: sW[k][ swz(eo,k) ] = W[n][eo][k]
    //      warp covers 8 consecutive eo (c=lane&7) x 4 consecutive k (r=lane>>3)
    //      -> STS banks = (((eo_hi^ (k&7))&3)*8 + c) all distinct: conflict-free
    {
        const float* wg = W + (size_t)n * (EO * II);
        const int c = l & 7;
        const int r = l >> 3;  // 0..3
        #pragma unroll 8
        for (int p = 0; p < 64; ++p) {
            int idx = w * 64 + p;            // 0..511
            int eo_hi = idx & 31;
            int k_hi = idx >> 5;
            int eo = eo_hi * 8 + c;
            int k  = k_hi * 4 + r;
            sW[k * 256 + (((eo_hi ^ (k & 7)) << 3) | c)] = wg[eo * 64 + k];
        }
    }
    __syncthreads();

    // ---- compute: acc[bp][j] = (out[b_even][eo_j], out[b_odd][eo_j])
    unsigned long long acc[4][8];
    #pragma unroll
    for (int i = 0; i < 4; ++i)
        #pragma unroll
        for (int j = 0; j < 8; ++j) acc[i][j] = 0ULL;

    const int bbase = w * 8;      // 8 b-rows per warp
    #pragma unroll 8
    for (int kk = 0; kk < 64; ++kk) {
        const int g = (l ^ (kk & 7)) << 3;             // swizzled eo-group
        const float4 w0 = *(const float4*)&sW[kk * 256 + g];
        const float4 w1 = *(const float4*)&sW[kk * 256 + g + 4];
        unsigned long long wd[8];
        wd[0] = dup2(w0.x); wd[1] = dup2(w0.y); wd[2] = dup2(w0.z); wd[3] = dup2(w0.w);
        wd[4] = dup2(w1.x); wd[5] = dup2(w1.y); wd[6] = dup2(w1.z); wd[7] = dup2(w1.w);
        const float* uk = &sU[kk * 66 + bbase];
        unsigned long long ub[4];
        #pragma unroll
        for (int bp = 0; bp < 4; ++bp)
            ub[bp] = *(const unsigned long long*)&uk[2 * bp];
        #pragma unroll
        for (int bp = 0; bp < 4; ++bp)
            #pragma unroll
            for (int j = 0; j < 8; ++j)
                ffma2(acc[bp][j], ub[bp], wd[j]);
    }

    // ---- epilogue: write u_hat[b][n][l*8 .. l*8+7]
    float* outp = g_u_hat + (size_t)n * EO + l * 8;
    #pragma unroll
    for (int bp = 0; bp < 4; ++bp) {
        float2 f0 = asf2(acc[bp][0]), f1 = asf2(acc[bp][1]);
        float2 f2 = asf2(acc[bp][2]), f3 = asf2(acc[bp][3]);
        float2 f4 = asf2(acc[bp][4]), f5 = asf2(acc[bp][5]);
        float2 f6 = asf2(acc[bp][6]), f7 = asf2(acc[bp][7]);
        int brow = bbase + 2 * bp;
        float* p0 = outp + (size_t)brow * NEO;
        float* p1 = p0 + (size_t)NEO;
        *(float4*)(p0)     = make_float4(f0.x, f1.x, f2.x, f3.x);
        *(float4*)(p0 + 4) = make_float4(f4.x, f5.x, f6.x, f7.x);
        *(float4*)(p1)     = make_float4(f0.y, f1.y, f2.y, f3.y);
        *(float4*)(p1 + 4) = make_float4(f4.y, f5.y, f6.y, f7.y);
    }
}

// ---------------------------------------------------------------------------
// Kernel 2: s0 partial = (1/8) * sum_{n in chunk} u_hat[b,n,:]
// grid 512 = 64 b x 8 chunks (128 n each). Deterministic (no atomics).
// ---------------------------------------------------------------------------
__global__ __launch_bounds__(256)
void reduce_s0_kernel() {
    const int b = blockIdx.x >> 3;
    const int chunk = blockIdx.x & 7;
    const int t = threadIdx.x;
    const float* p = g_u_hat + (size_t)b * NEO + (size_t)(chunk * 128) * EO + t;
    float acc = 0.f;
    #pragma unroll 8
    for (int i = 0; i < 128; ++i) acc += p[(size_t)i * EO];
    g_spart[chunk * (BB * EO) + b * EO + t] = acc * 0.125f;
}

// ---------------------------------------------------------------------------
// Kernel 3: squash. Sums the 8 partial slices, squashes per (b,e) 32-vector.
// ---------------------------------------------------------------------------
template <bool FINAL>
__global__ __launch_bounds__(256)
void squash_kernel(float* __restrict__ out) {
    const int t = threadIdx.x, w = t >> 5, l = t & 31;
    const int be = blockIdx.x * 8 + w;   // 0..511 = b*8+e
    const int idx = be * 32 + l;         // = b*256 + e*32 + o
    float x = 0.f;
    #pragma unroll
    for (int c = 0; c < 8; ++c) x += g_spart[c * (BB * EO) + idx];
    float n2 = x * x;
    n2 += __shfl_xor_sync(0xffffffffu, n2, 1);
    n2 += __shfl_xor_sync(0xffffffffu, n2, 2);
    n2 += __shfl_xor_sync(0xffffffffu, n2, 4);
    n2 += __shfl_xor_sync(0xffffffffu, n2, 8);
    n2 += __shfl_xor_sync(0xffffffffu, n2, 16);
    float nrm = sqrtf(n2);
    float scale = n2 / ((1.f + n2) * (nrm + 1e-8f));
    float v = x * scale;
    if (FINAL) out[idx] = v; else g_v[idx] = v;
}

// ---------------------------------------------------------------------------
// Kernel 4/5: fused routing iteration.
// One warp handles 16 n's of one b. Lane layout: e = lane>>2, og = lane&3,
// lane owns u_hat[b,n,e, og*8 .. og*8+7] (2x LDG.128, fully coalesced 1KB/n).
// Per n: uv (dot + xor{1,2}), logit update, softmax over E via xor{4,8,16},
// c*u_hat accumulation in registers. CTA-combine in SMEM, write g_spart slice.
// ---------------------------------------------------------------------------
template <int ITER>
__global__ __launch_bounds__(256)
void routing_kernel() {
    __shared__ float s_sh[8 * EO];
    const int b = blockIdx.x >> 3;
    const int chunk = blockIdx.x & 7;
    const int t = threadIdx.x, w = t >> 5, l = t & 31;
    const int e = l >> 2, og = l & 3;
    const int off = e * 32 + og * 8;

    const float4 v0 = *(const float4*)&g_v[b * EO + off];
    const float4 v1 = *(const float4*)&g_v[b * EO + off + 4];

    float acc0 = 0.f, acc1 = 0.f, acc2 = 0.f, acc3 = 0.f;
    float acc4 = 0.f, acc5 = 0.f, acc6 = 0.f, acc7 = 0.f;

    const int n0 = chunk * 128 + w * 16;
    const float* uh = g_u_hat + (size_t)b * NEO + (size_t)n0 * EO + off;
    float* bbp = g_b + b * (NN * EE) + n0 * EE;

    // software pipeline: prefetch next n while computing current
    float4 a0 = *(const float4*)uh;
    float4 a1 = *(const float4*)(uh + 4);
    #pragma unroll 4
    for (int nn = 0; nn < 16; ++nn) {
        const float4 c0 = a0, c1 = a1;
        float bprev = 0.f;
        if (ITER == 2) bprev = bbp[nn * EE + e];
        if (nn < 15) {
            const float* q = uh + (size_t)(nn + 1) * EO;
            a0 = *(const float4*)q;
            a1 = *(const float4*)(q + 4);
        }
        float dot = c0.x * v0.x + c0.y * v0.y + c0.z * v0.z + c0.w * v0.w
                  + c1.x * v1.x + c1.y * v1.y + c1.z * v1.z + c1.w * v1.w;
        dot += __shfl_xor_sync(0xffffffffu, dot, 1);
        dot += __shfl_xor_sync(0xffffffffu, dot, 2);
        float bn = dot;
        if (ITER == 2) bn += bprev;
        else if (og == 0) bbp[nn * EE + e] = bn;   // b1 = uv0 (b starts at 0)

        // softmax over E (lanes with same e hold identical values)
        float m = bn;
        m = fmaxf(m, __shfl_xor_sync(0xffffffffu, m, 4));
        m = fmaxf(m, __shfl_xor_sync(0xffffffffu, m, 8));
        m = fmaxf(m, __shfl_xor_sync(0xffffffffu, m, 16));
        float ex = __expf(bn - m);
        float sm = ex;
        sm += __shfl_xor_sync(0xffffffffu, sm, 4);
        sm += __shfl_xor_sync(0xffffffffu, sm, 8);
        sm += __shfl_xor_sync(0xffffffffu, sm, 16);   // = 4 * sum_e
        float c = __fdividef(4.f * ex, sm);

        acc0 += c * c0.x; acc1 += c * c0.y; acc2 += c * c0.z; acc3 += c * c0.w;
        acc4 += c * c1.x; acc5 += c * c1.y; acc6 += c * c1.z; acc7 += c * c1.w;
    }

    // per-warp slice (disjoint within warp -> deterministic)
    float* sw = &s_sh[w * EO + off];
    sw[0] = acc0; sw[1] = acc1; sw[2] = acc2; sw[3] = acc3;
    sw[4] = acc4; sw[5] = acc5; sw[6] = acc6; sw[7] = acc7;
    __syncthreads();
    float sum = 0.f;
    #pragma unroll
    for (int ww = 0; ww < 8; ++ww) sum += s_sh[ww * EO + t];
    g_spart[chunk * (BB * EO) + b * EO + t] = sum;
}

// ---------------------------------------------------------------------------
// Launch
// ---------------------------------------------------------------------------
extern "C" void kernel_launch(void* const* d_in, const int* in_sizes, int n_in,
                              void* d_out, int out_size) {
    const float* u = (const float*)d_in[0];
    const float* W = (const float*)d_in[1];
    if (n_in >= 2 && in_sizes[0] > in_sizes[1]) {  // u = 4.19M elems, W = 16.78M
        const float* tmp = u; u = W; W = tmp;
    }
    float* out = (float*)d_out;
    (void)out_size;

    cudaFuncSetAttribute(gemm_kernel,
                         cudaFuncAttributeMaxDynamicSharedMemorySize,
                         GEMM_SMEM_BYTES);

    gemm_kernel<<<NN, 256, GEMM_SMEM_BYTES>>>(u, W);   // u_hat
    reduce_s0_kernel<<<512, 256>>>();                  // s0 partials (c=1/8)
    squash_kernel<false><<<64, 256>>>(out);            // v0 -> g_v
    routing_kernel<1><<<512, 256>>>();                 // b1, s1 partials
    squash_kernel<false><<<64, 256>>>(out);            // v1 -> g_v
    routing_kernel<2><<<512, 256>>>();                 // b2, s2 partials
    squash_kernel<true><<<64, 256>>>(out);             // v2 -> d_out
}

// round 4
// speedup vs baseline: 1.2023x; 1.2023x over previous
#include <cuda_runtime.h>

// Problem dims (fixed by reference setup_inputs)
#define BB   64      // batch
#define NN   1024    // capsules in
#define EE   8       // capsules out
#define OO   32      // out_dim
#define II   64      // in_dim
#define EO   256     // EE*OO
#define NEO  (NN*EO) // per-batch u_hat stride = 262144
#define CH   16      // reduction chunks (grid = BB*CH)

// ---------------------------------------------------------------------------
// Scratch (device globals; no allocation allowed)
// ---------------------------------------------------------------------------
__device__ float g_u_hat[(size_t)BB * NN * EO];   // 64 MB   [b][n][eo]
__device__ float g_spart[CH * BB * EO];           // 1 MB    [chunk][b][eo]
__device__ float g_v[BB * EO];                    // v from squash
__device__ float g_b[BB * NN * EE];               // routing logits [b][n][e]

// ---------------------------------------------------------------------------
// fp32x2 packed helpers (PTX-only; ptxas never auto-fuses FFMA2)
// ---------------------------------------------------------------------------
__device__ __forceinline__ void ffma2(unsigned long long& d,
                                      unsigned long long a,
                                      unsigned long long b) {
    asm("fma.rn.f32x2 %0, %1, %2, %0;" : "+l"(d) : "l"(a), "l"(b));
}
__device__ __forceinline__ float2 asf2(unsigned long long v) {
    union { unsigned long long u; float2 f; } c; c.u = v; return c.f;
}

// ---------------------------------------------------------------------------
// Kernel 1: u_hat[b,n,eo] = sum_i W[n,eo,i] * u[b,n,i]
// One CTA per n, 256 threads, pair dimension = eo (f32x2).
// sW: [k][eo ^ ((k>>2 & 7)<<2)]  -- coalesced float4 fill, <=2-way STS,
//                                   conflict-free LDS.128 on compute.
// sUd: [k][2b{+0,1}] duplicated u -- FFMA2 operands load directly, no movs.
// Lane l owns eo {4l..4l+3, 4l+128..4l+131}; warp w owns b {8w..8w+7}.
// ---------------------------------------------------------------------------
#define SW_FLOATS  (64*256)          // 64 KB
#define SUD_FLOATS (64*128)          // 32 KB (duplicated pairs)
#define GEMM_SMEM_BYTES ((SW_FLOATS + SUD_FLOATS) * 4)

__global__ __launch_bounds__(256, 2)
void gemm_kernel(const float* __restrict__ u, const float* __restrict__ W) {
    extern __shared__ float smem[];
    float* sW  = smem;                 // [64][256] swizzled
    float* sUd = smem + SW_FLOATS;     // [64][128] dup'd

    const int n = blockIdx.x;
    const int t = threadIdx.x;
    const int w = t >> 5;
    const int l = t & 31;

    // ---- fill sW: coalesced float4 LDG, swizzled scatter STS (<=2-way)
    {
        const float4* wg4 = (const float4*)(W + (size_t)n * (EO * II));
        #pragma unroll
        for (int it = 0; it < 16; ++it) {
            int idx = t + it * 256;          // 0..4095 float4s
            int eo  = idx >> 4;              // 0..255
            int kf4 = idx & 15;              // float4 index within 64-float row
            float4 v = wg4[idx];
            int col  = eo ^ ((kf4 & 7) << 2);
            float* p = &sW[(kf4 * 4) * 256 + col];
            p[0]   = v.x;
            p[256] = v.y;
            p[512] = v.z;
            p[768] = v.w;
        }
    }
    // ---- fill sUd: duplicated pairs {u,u} so FFMA2 B-operand loads directly
    {
        const int b  = t >> 2;
        const int fq = t & 3;
        const float4* ug4 = (const float4*)(u + ((size_t)b * NN + n) * II);
        float2* sUd2 = (float2*)sUd;     // [64][64] in float2 units
        #pragma unroll
        for (int i = 0; i < 4; ++i) {
            int f = fq * 4 + i;              // 0..15
            float4 v = ug4[f];
            int k0 = f * 4;
            sUd2[(k0 + 0) * 64 + b] = make_float2(v.x, v.x);
            sUd2[(k0 + 1) * 64 + b] = make_float2(v.y, v.y);
            sUd2[(k0 + 2) * 64 + b] = make_float2(v.z, v.z);
            sUd2[(k0 + 3) * 64 + b] = make_float2(v.w, v.w);
        }
    }
    __syncthreads();

    // ---- compute: acc[r][p] = f32x2 over eo pair p for b = 8w+r
    unsigned long long acc[8][4];
    #pragma unroll
    for (int r = 0; r < 8; ++r)
        #pragma unroll
        for (int p = 0; p < 4; ++p) acc[r][p] = 0ULL;

    const float* ubase = &sUd[w * 16];

    #pragma unroll 4
    for (int k4 = 0; k4 < 16; ++k4) {
        const int X4 = (k4 & 7) << 2;
        const float* wbase = &sW[(4 * l) ^ X4];
        #pragma unroll
        for (int j = 0; j < 4; ++j) {
            const int k = k4 * 4 + j;
            const ulonglong2 w0 = *(const ulonglong2*)&wbase[k * 256];
            const ulonglong2 w1 = *(const ulonglong2*)&wbase[k * 256 + 128];
            const ulonglong2* ub = (const ulonglong2*)&ubase[k * 128];
            const ulonglong2 u0 = ub[0], u1 = ub[1], u2 = ub[2], u3 = ub[3];

            ffma2(acc[0][0], u0.x, w0.x); ffma2(acc[0][1], u0.x, w0.y);
            ffma2(acc[0][2], u0.x, w1.x); ffma2(acc[0][3], u0.x, w1.y);
            ffma2(acc[1][0], u0.y, w0.x); ffma2(acc[1][1], u0.y, w0.y);
            ffma2(acc[1][2], u0.y, w1.x); ffma2(acc[1][3], u0.y, w1.y);
            ffma2(acc[2][0], u1.x, w0.x); ffma2(acc[2][1], u1.x, w0.y);
            ffma2(acc[2][2], u1.x, w1.x); ffma2(acc[2][3], u1.x, w1.y);
            ffma2(acc[3][0], u1.y, w0.x); ffma2(acc[3][1], u1.y, w0.y);
            ffma2(acc[3][2], u1.y, w1.x); ffma2(acc[3][3], u1.y, w1.y);
            ffma2(acc[4][0], u2.x, w0.x); ffma2(acc[4][1], u2.x, w0.y);
            ffma2(acc[4][2], u2.x, w1.x); ffma2(acc[4][3], u2.x, w1.y);
            ffma2(acc[5][0], u2.y, w0.x); ffma2(acc[5][1], u2.y, w0.y);
            ffma2(acc[5][2], u2.y, w1.x); ffma2(acc[5][3], u2.y, w1.y);
            ffma2(acc[6][0], u3.x, w0.x); ffma2(acc[6][1], u3.x, w0.y);
            ffma2(acc[6][2], u3.x, w1.x); ffma2(acc[6][3], u3.x, w1.y);
            ffma2(acc[7][0], u3.y, w0.x); ffma2(acc[7][1], u3.y, w0.y);
            ffma2(acc[7][2], u3.y, w1.x); ffma2(acc[7][3], u3.y, w1.y);
        }
    }

    // ---- epilogue: lane writes eo 4l..4l+3 and 4l+128..4l+131, coalesced
    float* outp = g_u_hat + (size_t)n * EO + 4 * l;
    #pragma unroll
    for (int r = 0; r < 8; ++r) {
        float2 p0 = asf2(acc[r][0]), p1 = asf2(acc[r][1]);
        float2 p2 = asf2(acc[r][2]), p3 = asf2(acc[r][3]);
        float* pp = outp + (size_t)(w * 8 + r) * NEO;
        *(float4*)pp         = make_float4(p0.x, p0.y, p1.x, p1.y);
        *(float4*)(pp + 128) = make_float4(p2.x, p2.y, p3.x, p3.y);
    }
}

// ---------------------------------------------------------------------------
// Kernel 2: s0 partial = (1/8) * sum_{n in chunk} u_hat[b,n,:]
// grid 1024 = 64 b x 16 chunks (64 n each). Deterministic (no atomics).
// ---------------------------------------------------------------------------
__global__ __launch_bounds__(256)
void reduce_s0_kernel() {
    const int b = blockIdx.x >> 4;
    const int chunk = blockIdx.x & 15;
    const int t = threadIdx.x;
    const float* p = g_u_hat + (size_t)b * NEO + (size_t)(chunk * 64) * EO + t;
    float acc = 0.f;
    #pragma unroll 8
    for (int i = 0; i < 64; ++i) acc += p[(size_t)i * EO];
    g_spart[chunk * (BB * EO) + b * EO + t] = acc * 0.125f;
}

// ---------------------------------------------------------------------------
// Kernel 3: squash. Sums the CH partial slices, squashes per (b,e) 32-vector.
// ---------------------------------------------------------------------------
template <bool FINAL>
__global__ __launch_bounds__(256)
void squash_kernel(float* __restrict__ out) {
    const int t = threadIdx.x, w = t >> 5, l = t & 31;
    const int be = blockIdx.x * 8 + w;   // 0..511 = b*8+e
    const int idx = be * 32 + l;         // = b*256 + e*32 + o
    float x = 0.f;
    #pragma unroll
    for (int c = 0; c < CH; ++c) x += g_spart[c * (BB * EO) + idx];
    float n2 = x * x;
    n2 += __shfl_xor_sync(0xffffffffu, n2, 1);
    n2 += __shfl_xor_sync(0xffffffffu, n2, 2);
    n2 += __shfl_xor_sync(0xffffffffu, n2, 4);
    n2 += __shfl_xor_sync(0xffffffffu, n2, 8);
    n2 += __shfl_xor_sync(0xffffffffu, n2, 16);
    float nrm = sqrtf(n2);
    float scale = n2 / ((1.f + n2) * (nrm + 1e-8f));
    float v = x * scale;
    if (FINAL) out[idx] = v; else g_v[idx] = v;
}

// ---------------------------------------------------------------------------
// Kernel 4/5: fused routing iteration.
// grid 1024 = 64 b x 16 chunks. Warp handles 8 n (2 interleaved per step,
// pair-ahead prefetch -> 4 LDG.128 in flight per lane).
// Lane layout: e = lane>>2, og = lane&3; lane owns u_hat[b,n,e, og*8..+8).
// ---------------------------------------------------------------------------
template <int ITER>
__global__ __launch_bounds__(256)
void routing_kernel() {
    __shared__ float s_sh[8 * EO];
    const int b = blockIdx.x >> 4;
    const int chunk = blockIdx.x & 15;
    const int t = threadIdx.x, w = t >> 5, l = t & 31;
    const int e = l >> 2;
    const int og = l & 3;
    const int off = e * 32 + og * 8;

    const float4 v0 = *(const float4*)&g_v[b * EO + off];
    const float4 v1 = *(const float4*)&g_v[b * EO + off + 4];

    float acc[8];
    #pragma unroll
    for (int i = 0; i < 8; ++i) acc[i] = 0.f;

    const int n0 = chunk * 64 + w * 8;
    const float* uh = g_u_hat + (size_t)b * NEO + (size_t)n0 * EO + off;
    float* bbp = g_b + b * (NN * EE) + n0 * EE;

    float bpre[8];
    if (ITER == 2) {
        #pragma unroll
        for (int nn = 0; nn < 8; ++nn) bpre[nn] = bbp[nn * EE + e];
    }

    float4 A0 = *(const float4*)uh;
    float4 A1 = *(const float4*)(uh + 4);
    float4 B0 = *(const float4*)(uh + EO);
    float4 B1 = *(const float4*)(uh + EO + 4);

    #pragma unroll
    for (int s = 0; s < 4; ++s) {
        const float4 x0 = A0, x1 = A1, y0 = B0, y1 = B1;
        if (s < 3) {
            const float* q = uh + (size_t)(2 * s + 2) * EO;
            A0 = *(const float4*)q;
            A1 = *(const float4*)(q + 4);
            B0 = *(const float4*)(q + EO);
            B1 = *(const float4*)(q + EO + 4);
        }
        float d0 = x0.x * v0.x + x0.y * v0.y + x0.z * v0.z + x0.w * v0.w
                 + x1.x * v1.x + x1.y * v1.y + x1.z * v1.z + x1.w * v1.w;
        float d1 = y0.x * v0.x + y0.y * v0.y + y0.z * v0.z + y0.w * v0.w
                 + y1.x * v1.x + y1.y * v1.y + y1.z * v1.z + y1.w * v1.w;
        d0 += __shfl_xor_sync(0xffffffffu, d0, 1);
        d1 += __shfl_xor_sync(0xffffffffu, d1, 1);
        d0 += __shfl_xor_sync(0xffffffffu, d0, 2);
        d1 += __shfl_xor_sync(0xffffffffu, d1, 2);
        float bn0 = d0, bn1 = d1;
        if (ITER == 2) { bn0 += bpre[2 * s]; bn1 += bpre[2 * s + 1]; }
        else if (og == 0) {
            bbp[(2 * s) * EE + e]     = bn0;   // b1 = uv0 (b starts at 0)
            bbp[(2 * s + 1) * EE + e] = bn1;
        }

        // softmax over E (butterfly spans the 8 e-lanes; og lanes identical)
        float m0 = bn0, m1 = bn1;
        m0 = fmaxf(m0, __shfl_xor_sync(0xffffffffu, m0, 4));
        m1 = fmaxf(m1, __shfl_xor_sync(0xffffffffu, m1, 4));
        m0 = fmaxf(m0, __shfl_xor_sync(0xffffffffu, m0, 8));
        m1 = fmaxf(m1, __shfl_xor_sync(0xffffffffu, m1, 8));
        m0 = fmaxf(m0, __shfl_xor_sync(0xffffffffu, m0, 16));
        m1 = fmaxf(m1, __shfl_xor_sync(0xffffffffu, m1, 16));
        float ex0 = __expf(bn0 - m0);
        float ex1 = __expf(bn1 - m1);
        float sm0 = ex0, sm1 = ex1;
        sm0 += __shfl_xor_sync(0xffffffffu, sm0, 4);
        sm1 += __shfl_xor_sync(0xffffffffu, sm1, 4);
        sm0 += __shfl_xor_sync(0xffffffffu, sm0, 8);
        sm1 += __shfl_xor_sync(0xffffffffu, sm1, 8);
        sm0 += __shfl_xor_sync(0xffffffffu, sm0, 16);
        sm1 += __shfl_xor_sync(0xffffffffu, sm1, 16);
        const float c0 = __fdividef(ex0, sm0);   // true softmax over E
        const float c1 = __fdividef(ex1, sm1);

        acc[0] += c0 * x0.x + c1 * y0.x;
        acc[1] += c0 * x0.y + c1 * y0.y;
        acc[2] += c0 * x0.z + c1 * y0.z;
        acc[3] += c0 * x0.w + c1 * y0.w;
        acc[4] += c0 * x1.x + c1 * y1.x;
        acc[5] += c0 * x1.y + c1 * y1.y;
        acc[6] += c0 * x1.z + c1 * y1.z;
        acc[7] += c0 * x1.w + c1 * y1.w;
    }

    // per-warp slice (disjoint within warp -> deterministic)
    float* sw = &s_sh[w * EO + off];
    #pragma unroll
    for (int i = 0; i < 8; ++i) sw[i] = acc[i];
    __syncthreads();
    float sum = 0.f;
    #pragma unroll
    for (int ww = 0; ww < 8; ++ww) sum += s_sh[ww * EO + t];
    g_spart[chunk * (BB * EO) + b * EO + t] = sum;
}

// ---------------------------------------------------------------------------
// Launch
// ---------------------------------------------------------------------------
extern "C" void kernel_launch(void* const* d_in, const int* in_sizes, int n_in,
                              void* d_out, int out_size) {
    const float* u = (const float*)d_in[0];
    const float* W = (const float*)d_in[1];
    if (n_in >= 2 && in_sizes[0] > in_sizes[1]) {  // u = 4.19M elems, W = 16.78M
        const float* tmp = u; u = W; W = tmp;
    }
    float* out = (float*)d_out;
    (void)out_size;

    cudaFuncSetAttribute(gemm_kernel,
                         cudaFuncAttributeMaxDynamicSharedMemorySize,
                         GEMM_SMEM_BYTES);

    gemm_kernel<<<NN, 256, GEMM_SMEM_BYTES>>>(u, W);   // u_hat
    reduce_s0_kernel<<<BB * CH, 256>>>();              // s0 partials (c=1/8)
    squash_kernel<false><<<64, 256>>>(out);            // v0 -> g_v
    routing_kernel<1><<<BB * CH, 256>>>();             // b1, s1 partials
    squash_kernel<false><<<64, 256>>>(out);            // v1 -> g_v
    routing_kernel<2><<<BB * CH, 256>>>();             // b2, s2 partials
    squash_kernel<true><<<64, 256>>>(out);             // v2 -> d_out
}

// round 6
// speedup vs baseline: 1.4005x; 1.1649x over previous
#include <cuda_runtime.h>
#include <cuda_fp16.h>

// Problem dims (fixed by reference setup_inputs)
#define BB   64      // batch
#define NN   1024    // capsules in
#define EE   8       // capsules out
#define OO   32      // out_dim
#define II   64      // in_dim
#define EO   256     // EE*OO
#define NEO  (NN*EO) // per-batch u_hat stride = 262144
#define CH   16      // reduction chunks

// ---------------------------------------------------------------------------
// Scratch (device globals; no allocation allowed)
// ---------------------------------------------------------------------------
__device__ __half g_u_hat[(size_t)BB * NN * EO];          // 32 MB [b][n][eo]
__device__ float g_spart[CH * BB * EO];                   // 1 MB  [chunk][b][eo]
__device__ float g_b[BB * NN * EE];                       // logits [b][n][e]

// ---------------------------------------------------------------------------
// fp32x2 / fp16 packed helpers
// ---------------------------------------------------------------------------
__device__ __forceinline__ void ffma2(unsigned long long& d,
                                      unsigned long long a,
                                      unsigned long long b) {
    asm("fma.rn.f32x2 %0, %1, %2, %0;" : "+l"(d) : "l"(a), "l"(b));
}
__device__ __forceinline__ float2 asf2(unsigned long long v) {
    union { unsigned long long u; float2 f; } c; c.u = v; return c.f;
}
// pack two floats into f16x2 with `lo` in the low half (memory-first elem)
__device__ __forceinline__ unsigned pack_f16(float lo, float hi) {
    unsigned r;
    asm("cvt.rn.f16x2.f32 %0, %1, %2;" : "=r"(r) : "f"(hi), "f"(lo));
    return r;
}

// ---------------------------------------------------------------------------
// Kernel 1: u_hat[b,n,eo] = sum_i W[n,eo,i] * u[b,n,i]   (fp16 output)
// One CTA per n, 256 threads, pair dimension = eo (f32x2 accum).
// sW: [k][eo ^ ((k>>2 & 7)<<2)] swizzle; sUd: duplicated {u,u} pairs.
// Lane l owns eo {4l..4l+3, 4l+128..4l+131}; warp w owns b {8w..8w+7}.
// ---------------------------------------------------------------------------
#define SW_FLOATS  (64*256)
#define SUD_FLOATS (64*128)
#define GEMM_SMEM_BYTES ((SW_FLOATS + SUD_FLOATS) * 4)

__global__ __launch_bounds__(256, 2)
void gemm_kernel(const float* __restrict__ u, const float* __restrict__ W) {
    extern __shared__ float smem[];
    float* sW  = smem;                 // [64][256] swizzled
    float* sUd = smem + SW_FLOATS;     // [64][128] dup'd

    const int n = blockIdx.x;
    const int t = threadIdx.x;
    const int w = t >> 5;
    const int l = t & 31;

    // ---- fill sW: coalesced float4 LDG, swizzled scatter STS (<=2-way)
    {
        const float4* wg4 = (const float4*)(W + (size_t)n * (EO * II));
        #pragma unroll
        for (int it = 0; it < 16; ++it) {
            int idx = t + it * 256;          // 0..4095 float4s
            int eo  = idx >> 4;
            int kf4 = idx & 15;
            float4 v = wg4[idx];
            int col  = eo ^ ((kf4 & 7) << 2);
            float* p = &sW[(kf4 * 4) * 256 + col];
            p[0]   = v.x;
            p[256] = v.y;
            p[512] = v.z;
            p[768] = v.w;
        }
    }
    // ---- fill sUd: duplicated pairs {u,u} -> FFMA2 B-operand loads directly
    {
        const int b  = t >> 2;
        const int fq = t & 3;
        const float4* ug4 = (const float4*)(u + ((size_t)b * NN + n) * II);
        float2* sUd2 = (float2*)sUd;     // [64][64] in float2 units
        #pragma unroll
        for (int i = 0; i < 4; ++i) {
            int f = fq * 4 + i;
            float4 v = ug4[f];
            int k0 = f * 4;
            sUd2[(k0 + 0) * 64 + b] = make_float2(v.x, v.x);
            sUd2[(k0 + 1) * 64 + b] = make_float2(v.y, v.y);
            sUd2[(k0 + 2) * 64 + b] = make_float2(v.z, v.z);
            sUd2[(k0 + 3) * 64 + b] = make_float2(v.w, v.w);
        }
    }
    __syncthreads();

    unsigned long long acc[8][4];
    #pragma unroll
    for (int r = 0; r < 8; ++r)
        #pragma unroll
        for (int p = 0; p < 4; ++p) acc[r][p] = 0ULL;

    const float* ubase = &sUd[w * 16];

    #pragma unroll 4
    for (int k4 = 0; k4 < 16; ++k4) {
        const int X4 = (k4 & 7) << 2;
        const float* wbase = &sW[(4 * l) ^ X4];
        #pragma unroll
        for (int j = 0; j < 4; ++j) {
            const int k = k4 * 4 + j;
            const ulonglong2 w0 = *(const ulonglong2*)&wbase[k * 256];
            const ulonglong2 w1 = *(const ulonglong2*)&wbase[k * 256 + 128];
            const ulonglong2* ub = (const ulonglong2*)&ubase[k * 128];
            const ulonglong2 u0 = ub[0], u1 = ub[1], u2 = ub[2], u3 = ub[3];

            ffma2(acc[0][0], u0.x, w0.x); ffma2(acc[0][1], u0.x, w0.y);
            ffma2(acc[0][2], u0.x, w1.x); ffma2(acc[0][3], u0.x, w1.y);
            ffma2(acc[1][0], u0.y, w0.x); ffma2(acc[1][1], u0.y, w0.y);
            ffma2(acc[1][2], u0.y, w1.x); ffma2(acc[1][3], u0.y, w1.y);
            ffma2(acc[2][0], u1.x, w0.x); ffma2(acc[2][1], u1.x, w0.y);
            ffma2(acc[2][2], u1.x, w1.x); ffma2(acc[2][3], u1.x, w1.y);
            ffma2(acc[3][0], u1.y, w0.x); ffma2(acc[3][1], u1.y, w0.y);
            ffma2(acc[3][2], u1.y, w1.x); ffma2(acc[3][3], u1.y, w1.y);
            ffma2(acc[4][0], u2.x, w0.x); ffma2(acc[4][1], u2.x, w0.y);
            ffma2(acc[4][2], u2.x, w1.x); ffma2(acc[4][3], u2.x, w1.y);
            ffma2(acc[5][0], u2.y, w0.x); ffma2(acc[5][1], u2.y, w0.y);
            ffma2(acc[5][2], u2.y, w1.x); ffma2(acc[5][3], u2.y, w1.y);
            ffma2(acc[6][0], u3.x, w0.x); ffma2(acc[6][1], u3.x, w0.y);
            ffma2(acc[6][2], u3.x, w1.x); ffma2(acc[6][3], u3.x, w1.y);
            ffma2(acc[7][0], u3.y, w0.x); ffma2(acc[7][1], u3.y, w0.y);
            ffma2(acc[7][2], u3.y, w1.x); ffma2(acc[7][3], u3.y, w1.y);
        }
    }

    // ---- epilogue: fp16 stores; lane writes eo 4l..4l+3 and +128, coalesced
    __half* outp = g_u_hat + (size_t)n * EO + 4 * l;
    #pragma unroll
    for (int r = 0; r < 8; ++r) {
        float2 p0 = asf2(acc[r][0]), p1 = asf2(acc[r][1]);
        float2 p2 = asf2(acc[r][2]), p3 = asf2(acc[r][3]);
        __half* pp = outp + (size_t)(w * 8 + r) * NEO;
        uint2 lo, hi;
        lo.x = pack_f16(p0.x, p0.y); lo.y = pack_f16(p1.x, p1.y);
        hi.x = pack_f16(p2.x, p2.y); hi.y = pack_f16(p3.x, p3.y);
        *(uint2*)pp         = lo;
        *(uint2*)(pp + 128) = hi;
    }
}

// ---------------------------------------------------------------------------
// Kernel 2: s0 partial = (1/8) * sum_{n in chunk} u_hat[b,n,:]
// grid 1024 = 64 b x 16 chunks (64 n each), 128 threads (eo pairs).
// ---------------------------------------------------------------------------
__global__ __launch_bounds__(128)
void reduce_s0_kernel() {
    const int b = blockIdx.x >> 4;
    const int chunk = blockIdx.x & 15;
    const int t = threadIdx.x;   // eo pair index 0..127
    const __half2* p = (const __half2*)
        (g_u_hat + (size_t)b * NEO + (size_t)(chunk * 64) * EO) + t;
    float ax = 0.f, ay = 0.f;
    #pragma unroll 16
    for (int i = 0; i < 64; ++i) {
        float2 f = __half22float2(p[(size_t)i * 128]);
        ax += f.x; ay += f.y;
    }
    float* q = &g_spart[chunk * (BB * EO) + b * EO + 2 * t];
    q[0] = ax * 0.125f;
    q[1] = ay * 0.125f;
}

// ---------------------------------------------------------------------------
// Kernel 3 (final only): squash partial sums -> d_out
// ---------------------------------------------------------------------------
__global__ __launch_bounds__(256)
void squash_final_kernel(float* __restrict__ out) {
    const int t = threadIdx.x, w = t >> 5, l = t & 31;
    const int be = blockIdx.x * 8 + w;
    const int idx = be * 32 + l;
    float x = 0.f;
    #pragma unroll
    for (int c = 0; c < CH; ++c) x += g_spart[c * (BB * EO) + idx];
    float n2 = x * x;
    n2 += __shfl_xor_sync(0xffffffffu, n2, 1);
    n2 += __shfl_xor_sync(0xffffffffu, n2, 2);
    n2 += __shfl_xor_sync(0xffffffffu, n2, 4);
    n2 += __shfl_xor_sync(0xffffffffu, n2, 8);
    n2 += __shfl_xor_sync(0xffffffffu, n2, 16);
    float nrm = sqrtf(n2);
    float scale = n2 / ((1.f + n2) * (nrm + 1e-8f));
    out[idx] = x * scale;
}

// ---------------------------------------------------------------------------
// Kernel 4/5: fused routing iteration (squash prologue + agreement + softmax
// + weighted accumulation). grid 1024 = 64 b x 16 chunks, 256 threads.
// Prologue: CTA recomputes v[b] from g_spart (deterministic, 16 KB read).
// Main: warp handles 8 n; lane l owns u_hat[b,n, 8l..8l+8) (one 16B fp16 LDG).
// ---------------------------------------------------------------------------
template <int ITER>
__global__ __launch_bounds__(256)
void routing_kernel() {
    __shared__ float s_v[EO];
    __shared__ float s_sh[8 * EO];
    const int b = blockIdx.x >> 4;
    const int chunk = blockIdx.x & 15;
    const int t = threadIdx.x, w = t >> 5, l = t & 31;
    const int e = l >> 2;

    // ---- prologue: v[b] = squash(sum_c spart[c][b][:])
    {
        float x = 0.f;
        #pragma unroll
        for (int c = 0; c < CH; ++c) x += g_spart[c * (BB * EO) + b * EO + t];
        float n2 = x * x;
        n2 += __shfl_xor_sync(0xffffffffu, n2, 1);
        n2 += __shfl_xor_sync(0xffffffffu, n2, 2);
        n2 += __shfl_xor_sync(0xffffffffu, n2, 4);
        n2 += __shfl_xor_sync(0xffffffffu, n2, 8);
        n2 += __shfl_xor_sync(0xffffffffu, n2, 16);
        float nrm = sqrtf(n2);
        float scale = n2 / ((1.f + n2) * (nrm + 1e-8f));
        s_v[t] = x * scale;
    }
    __syncthreads();

    const float4 v0 = *(const float4*)&s_v[8 * l];
    const float4 v1 = *(const float4*)&s_v[8 * l + 4];

    float acc[8];
    #pragma unroll
    for (int i = 0; i < 8; ++i) acc[i] = 0.f;

    const int n0 = chunk * 64 + w * 8;
    const uint4* uh = (const uint4*)
        (g_u_hat + (size_t)b * NEO + (size_t)n0 * EO + 8 * l);  // row step 32 uint4
    float* bbp = g_b + b * (NN * EE) + n0 * EE;

    float bpre[8];
    if (ITER == 2) {
        #pragma unroll
        for (int nn = 0; nn < 8; ++nn) bpre[nn] = bbp[nn * EE + e];
    }

    uint4 A = uh[0];
    uint4 B = uh[32];

    #pragma unroll
    for (int s = 0; s < 4; ++s) {
        const uint4 xa = A, xb = B;
        if (s < 3) {
            A = uh[(size_t)(2 * s + 2) * 32];
            B = uh[(size_t)(2 * s + 3) * 32];
        }
        float fx[8], fy[8];
        {
            float2 f;
            f = __half22float2(*(const __half2*)&xa.x); fx[0]=f.x; fx[1]=f.y;
            f = __half22float2(*(const __half2*)&xa.y); fx[2]=f.x; fx[3]=f.y;
            f = __half22float2(*(const __half2*)&xa.z); fx[4]=f.x; fx[5]=f.y;
            f = __half22float2(*(const __half2*)&xa.w); fx[6]=f.x; fx[7]=f.y;
            f = __half22float2(*(const __half2*)&xb.x); fy[0]=f.x; fy[1]=f.y;
            f = __half22float2(*(const __half2*)&xb.y); fy[2]=f.x; fy[3]=f.y;
            f = __half22float2(*(const __half2*)&xb.z); fy[4]=f.x; fy[5]=f.y;
            f = __half22float2(*(const __half2*)&xb.w); fy[6]=f.x; fy[7]=f.y;
        }
        float d0 = fx[0]*v0.x + fx[1]*v0.y + fx[2]*v0.z + fx[3]*v0.w
                 + fx[4]*v1.x + fx[5]*v1.y + fx[6]*v1.z + fx[7]*v1.w;
        float d1 = fy[0]*v0.x + fy[1]*v0.y + fy[2]*v0.z + fy[3]*v0.w
                 + fy[4]*v1.x + fy[5]*v1.y + fy[6]*v1.z + fy[7]*v1.w;
        d0 += __shfl_xor_sync(0xffffffffu, d0, 1);
        d1 += __shfl_xor_sync(0xffffffffu, d1, 1);
        d0 += __shfl_xor_sync(0xffffffffu, d0, 2);
        d1 += __shfl_xor_sync(0xffffffffu, d1, 2);
        float bn0 = d0, bn1 = d1;
        if (ITER == 2) { bn0 += bpre[2 * s]; bn1 += bpre[2 * s + 1]; }
        else if ((l & 3) == 0) {
            bbp[(2 * s) * EE + e]     = bn0;   // b1 = uv0 (b starts at 0)
            bbp[(2 * s + 1) * EE + e] = bn1;
        }

        // softmax over E (butterfly spans the 8 e-lanes; og lanes identical)
        float m0 = bn0, m1 = bn1;
        m0 = fmaxf(m0, __shfl_xor_sync(0xffffffffu, m0, 4));
        m1 = fmaxf(m1, __shfl_xor_sync(0xffffffffu, m1, 4));
        m0 = fmaxf(m0, __shfl_xor_sync(0xffffffffu, m0, 8));
        m1 = fmaxf(m1, __shfl_xor_sync(0xffffffffu, m1, 8));
        m0 = fmaxf(m0, __shfl_xor_sync(0xffffffffu, m0, 16));
        m1 = fmaxf(m1, __shfl_xor_sync(0xffffffffu, m1, 16));
        float ex0 = __expf(bn0 - m0);
        float ex1 = __expf(bn1 - m1);
        float sm0 = ex0, sm1 = ex1;
        sm0 += __shfl_xor_sync(0xffffffffu, sm0, 4);
        sm1 += __shfl_xor_sync(0xffffffffu, sm1, 4);
        sm0 += __shfl_xor_sync(0xffffffffu, sm0, 8);
        sm1 += __shfl_xor_sync(0xffffffffu, sm1, 8);
        sm0 += __shfl_xor_sync(0xffffffffu, sm0, 16);
        sm1 += __shfl_xor_sync(0xffffffffu, sm1, 16);
        const float c0 = __fdividef(ex0, sm0);
        const float c1 = __fdividef(ex1, sm1);

        #pragma unroll
        for (int i = 0; i < 8; ++i) acc[i] += c0 * fx[i] + c1 * fy[i];
    }

    // per-warp slice (disjoint within warp -> deterministic)
    float* sw = &s_sh[w * EO + 8 * l];
    #pragma unroll
    for (int i = 0; i < 8; ++i) sw[i] = acc[i];
    __syncthreads();
    float sum = 0.f;
    #pragma unroll
    for (int ww = 0; ww < 8; ++ww) sum += s_sh[ww * EO + t];
    g_spart[chunk * (BB * EO) + b * EO + t] = sum;
}

// ---------------------------------------------------------------------------
// Launch
// ---------------------------------------------------------------------------
extern "C" void kernel_launch(void* const* d_in, const int* in_sizes, int n_in,
                              void* d_out, int out_size) {
    const float* u = (const float*)d_in[0];
    const float* W = (const float*)d_in[1];
    if (n_in >= 2 && in_sizes[0] > in_sizes[1]) {  // u = 4.19M elems, W = 16.78M
        const float* tmp = u; u = W; W = tmp;
    }
    float* out = (float*)d_out;
    (void)out_size;

    cudaFuncSetAttribute(gemm_kernel,
                         cudaFuncAttributeMaxDynamicSharedMemorySize,
                         GEMM_SMEM_BYTES);

    gemm_kernel<<<NN, 256, GEMM_SMEM_BYTES>>>(u, W);   // u_hat (fp16)
    reduce_s0_kernel<<<BB * CH, 128>>>();              // s0 partials (c=1/8)
    routing_kernel<1><<<BB * CH, 256>>>();             // v0 prologue, b1, s1
    routing_kernel<2><<<BB * CH, 256>>>();             // v1 prologue, b2, s2
    squash_final_kernel<<<64, 256>>>(out);             // v2 -> d_out
}

// round 7
// speedup vs baseline: 1.4109x; 1.0074x over previous
#include <cuda_runtime.h>
#include <cuda_fp16.h>

// Problem dims (fixed by reference setup_inputs)
#define BB   64      // batch
#define NN   1024    // capsules in
#define EE   8       // capsules out
#define OO   32      // out_dim
#define II   64      // in_dim
#define EO   256     // EE*OO
#define NEO  (NN*EO) // per-batch u_hat stride = 262144
#define CH   16      // reduction chunks

// ---------------------------------------------------------------------------
// Scratch (device globals; no allocation allowed)
// ---------------------------------------------------------------------------
__device__ __half g_u_hat[(size_t)BB * NN * EO];          // 32 MB [b][n][eo]
__device__ float g_spart[CH * BB * EO];                   // 1 MB  [chunk][b][eo]
__device__ float g_b[BB * NN * EE];                       // logits [b][n][e]

// ---------------------------------------------------------------------------
// fp32x2 / fp16 packed helpers
// ---------------------------------------------------------------------------
__device__ __forceinline__ void ffma2(unsigned long long& d,
                                      unsigned long long a,
                                      unsigned long long b) {
    asm("fma.rn.f32x2 %0, %1, %2, %0;" : "+l"(d) : "l"(a), "l"(b));
}
__device__ __forceinline__ float2 asf2(unsigned long long v) {
    union { unsigned long long u; float2 f; } c; c.u = v; return c.f;
}
// pack two floats into f16x2 with `lo` in the low half (memory-first elem)
__device__ __forceinline__ unsigned pack_f16(float lo, float hi) {
    unsigned r;
    asm("cvt.rn.f16x2.f32 %0, %1, %2;" : "=r"(r) : "f"(hi), "f"(lo));
    return r;
}

// ---------------------------------------------------------------------------
// Kernel 1: u_hat[b,n,eo] = sum_i W[n,eo,i] * u[b,n,i]   (fp16 output)
// (unchanged from round 5 — FMA-issue bound ~45us; tcgen05 rewrite next round)
// ---------------------------------------------------------------------------
#define SW_FLOATS  (64*256)
#define SUD_FLOATS (64*128)
#define GEMM_SMEM_BYTES ((SW_FLOATS + SUD_FLOATS) * 4)

__global__ __launch_bounds__(256, 2)
void gemm_kernel(const float* __restrict__ u, const float* __restrict__ W) {
    extern __shared__ float smem[];
    float* sW  = smem;                 // [64][256] swizzled
    float* sUd = smem + SW_FLOATS;     // [64][128] dup'd

    const int n = blockIdx.x;
    const int t = threadIdx.x;
    const int w = t >> 5;
    const int l = t & 31;

    // ---- fill sW: coalesced float4 LDG, swizzled scatter STS (<=2-way)
    {
        const float4* wg4 = (const float4*)(W + (size_t)n * (EO * II));
        #pragma unroll
        for (int it = 0; it < 16; ++it) {
            int idx = t + it * 256;          // 0..4095 float4s
            int eo  = idx >> 4;
            int kf4 = idx & 15;
            float4 v = wg4[idx];
            int col  = eo ^ ((kf4 & 7) << 2);
            float* p = &sW[(kf4 * 4) * 256 + col];
            p[0]   = v.x;
            p[256] = v.y;
            p[512] = v.z;
            p[768] = v.w;
        }
    }
    // ---- fill sUd: duplicated pairs {u,u} -> FFMA2 B-operand loads directly
    {
        const int b  = t >> 2;
        const int fq = t & 3;
        const float4* ug4 = (const float4*)(u + ((size_t)b * NN + n) * II);
        float2* sUd2 = (float2*)sUd;     // [64][64] in float2 units
        #pragma unroll
        for (int i = 0; i < 4; ++i) {
            int f = fq * 4 + i;
            float4 v = ug4[f];
            int k0 = f * 4;
            sUd2[(k0 + 0) * 64 + b] = make_float2(v.x, v.x);
            sUd2[(k0 + 1) * 64 + b] = make_float2(v.y, v.y);
            sUd2[(k0 + 2) * 64 + b] = make_float2(v.z, v.z);
            sUd2[(k0 + 3) * 64 + b] = make_float2(v.w, v.w);
        }
    }
    __syncthreads();

    unsigned long long acc[8][4];
    #pragma unroll
    for (int r = 0; r < 8; ++r)
        #pragma unroll
        for (int p = 0; p < 4; ++p) acc[r][p] = 0ULL;

    const float* ubase = &sUd[w * 16];

    #pragma unroll 4
    for (int k4 = 0; k4 < 16; ++k4) {
        const int X4 = (k4 & 7) << 2;
        const float* wbase = &sW[(4 * l) ^ X4];
        #pragma unroll
        for (int j = 0; j < 4; ++j) {
            const int k = k4 * 4 + j;
            const ulonglong2 w0 = *(const ulonglong2*)&wbase[k * 256];
            const ulonglong2 w1 = *(const ulonglong2*)&wbase[k * 256 + 128];
            const ulonglong2* ub = (const ulonglong2*)&ubase[k * 128];
            const ulonglong2 u0 = ub[0], u1 = ub[1], u2 = ub[2], u3 = ub[3];

            ffma2(acc[0][0], u0.x, w0.x); ffma2(acc[0][1], u0.x, w0.y);
            ffma2(acc[0][2], u0.x, w1.x); ffma2(acc[0][3], u0.x, w1.y);
            ffma2(acc[1][0], u0.y, w0.x); ffma2(acc[1][1], u0.y, w0.y);
            ffma2(acc[1][2], u0.y, w1.x); ffma2(acc[1][3], u0.y, w1.y);
            ffma2(acc[2][0], u1.x, w0.x); ffma2(acc[2][1], u1.x, w0.y);
            ffma2(acc[2][2], u1.x, w1.x); ffma2(acc[2][3], u1.x, w1.y);
            ffma2(acc[3][0], u1.y, w0.x); ffma2(acc[3][1], u1.y, w0.y);
            ffma2(acc[3][2], u1.y, w1.x); ffma2(acc[3][3], u1.y, w1.y);
            ffma2(acc[4][0], u2.x, w0.x); ffma2(acc[4][1], u2.x, w0.y);
            ffma2(acc[4][2], u2.x, w1.x); ffma2(acc[4][3], u2.x, w1.y);
            ffma2(acc[5][0], u2.y, w0.x); ffma2(acc[5][1], u2.y, w0.y);
            ffma2(acc[5][2], u2.y, w1.x); ffma2(acc[5][3], u2.y, w1.y);
            ffma2(acc[6][0], u3.x, w0.x); ffma2(acc[6][1], u3.x, w0.y);
            ffma2(acc[6][2], u3.x, w1.x); ffma2(acc[6][3], u3.x, w1.y);
            ffma2(acc[7][0], u3.y, w0.x); ffma2(acc[7][1], u3.y, w0.y);
            ffma2(acc[7][2], u3.y, w1.x); ffma2(acc[7][3], u3.y, w1.y);
        }
    }

    // ---- epilogue: fp16 stores; lane writes eo 4l..4l+3 and +128, coalesced
    __half* outp = g_u_hat + (size_t)n * EO + 4 * l;
    #pragma unroll
    for (int r = 0; r < 8; ++r) {
        float2 p0 = asf2(acc[r][0]), p1 = asf2(acc[r][1]);
        float2 p2 = asf2(acc[r][2]), p3 = asf2(acc[r][3]);
        __half* pp = outp + (size_t)(w * 8 + r) * NEO;
        uint2 lo, hi;
        lo.x = pack_f16(p0.x, p0.y); lo.y = pack_f16(p1.x, p1.y);
        hi.x = pack_f16(p2.x, p2.y); hi.y = pack_f16(p3.x, p3.y);
        *(uint2*)pp         = lo;
        *(uint2*)(pp + 128) = hi;
    }
}

// ---------------------------------------------------------------------------
// Kernel 2: s0 partial = (1/8) * sum_{n in chunk} u_hat[b,n,:]
// grid 1024 = 64 b x 16 chunks (64 n each), 256 threads.
// Thread (nl = t>>5, q = t&31) sums eo-octet q over n = n0+nl+8j (j=0..7):
// warp-coalesced uint4 loads, 8 in flight. SMEM 8-way combine across nl.
// ---------------------------------------------------------------------------
__global__ __launch_bounds__(256)
void reduce_s0_kernel() {
    __shared__ float s_sh[8 * EO];
    const int b = blockIdx.x >> 4;
    const int chunk = blockIdx.x & 15;
    const int t = threadIdx.x;
    const int nl = t >> 5;       // 0..7
    const int q  = t & 31;       // eo octet

    const uint4* base = (const uint4*)
        (g_u_hat + (size_t)b * NEO + (size_t)(chunk * 64) * EO);
    uint4 r[8];
    #pragma unroll
    for (int j = 0; j < 8; ++j)
        r[j] = base[(size_t)(nl + 8 * j) * 32 + q];

    float acc[8];
    #pragma unroll
    for (int i = 0; i < 8; ++i) acc[i] = 0.f;
    #pragma unroll
    for (int j = 0; j < 8; ++j) {
        float2 f;
        f = __half22float2(*(const __half2*)&r[j].x); acc[0]+=f.x; acc[1]+=f.y;
        f = __half22float2(*(const __half2*)&r[j].y); acc[2]+=f.x; acc[3]+=f.y;
        f = __half22float2(*(const __half2*)&r[j].z); acc[4]+=f.x; acc[5]+=f.y;
        f = __half22float2(*(const __half2*)&r[j].w); acc[6]+=f.x; acc[7]+=f.y;
    }
    float* sw = &s_sh[nl * EO + 8 * q];
    #pragma unroll
    for (int i = 0; i < 8; ++i) sw[i] = acc[i];
    __syncthreads();
    float sum = 0.f;
    #pragma unroll
    for (int ww = 0; ww < 8; ++ww) sum += s_sh[ww * EO + t];
    g_spart[chunk * (BB * EO) + b * EO + t] = sum * 0.125f;
}

// ---------------------------------------------------------------------------
// Kernel 3 (final only): squash partial sums -> d_out
// ---------------------------------------------------------------------------
__global__ __launch_bounds__(256)
void squash_final_kernel(float* __restrict__ out) {
    const int t = threadIdx.x, w = t >> 5, l = t & 31;
    const int be = blockIdx.x * 8 + w;
    const int idx = be * 32 + l;
    float x = 0.f;
    #pragma unroll
    for (int c = 0; c < CH; ++c) x += g_spart[c * (BB * EO) + idx];
    float n2 = x * x;
    n2 += __shfl_xor_sync(0xffffffffu, n2, 1);
    n2 += __shfl_xor_sync(0xffffffffu, n2, 2);
    n2 += __shfl_xor_sync(0xffffffffu, n2, 4);
    n2 += __shfl_xor_sync(0xffffffffu, n2, 8);
    n2 += __shfl_xor_sync(0xffffffffu, n2, 16);
    float nrm = sqrtf(n2);
    float scale = n2 / ((1.f + n2) * (nrm + 1e-8f));
    out[idx] = x * scale;
}

// ---------------------------------------------------------------------------
// Kernel 4/5: fused routing iteration. grid 1024 = 64 b x 16 chunks, 256 thr.
// Prologue: CTA recomputes v[b] from g_spart.
// Main: warp handles 8 n; ALL 8 row-loads issued up-front (4 KB in flight
// per warp -> Little's-law satisfied; kernel becomes DRAM-BW bound).
// ---------------------------------------------------------------------------
template <int ITER>
__global__ __launch_bounds__(256)
void routing_kernel() {
    __shared__ float s_v[EO];
    __shared__ float s_sh[8 * EO];
    const int b = blockIdx.x >> 4;
    const int chunk = blockIdx.x & 15;
    const int t = threadIdx.x, w = t >> 5, l = t & 31;
    const int e = l >> 2;

    const int n0 = chunk * 64 + w * 8;
    const uint4* uh = (const uint4*)
        (g_u_hat + (size_t)b * NEO + (size_t)n0 * EO + 8 * l);  // row step 32 uint4

    // ---- issue ALL u_hat loads first (MLP=8 per lane)
    uint4 A[8];
    #pragma unroll
    for (int nn = 0; nn < 8; ++nn) A[nn] = uh[(size_t)nn * 32];

    float* bbp = g_b + b * (NN * EE) + n0 * EE;
    float bpre[8];
    if (ITER == 2) {
        #pragma unroll
        for (int nn = 0; nn < 8; ++nn) bpre[nn] = bbp[nn * EE + e];
    }

    // ---- prologue: v[b] = squash(sum_c spart[c][b][:])  (overlaps loads)
    {
        float x = 0.f;
        #pragma unroll
        for (int c = 0; c < CH; ++c) x += g_spart[c * (BB * EO) + b * EO + t];
        float n2 = x * x;
        n2 += __shfl_xor_sync(0xffffffffu, n2, 1);
        n2 += __shfl_xor_sync(0xffffffffu, n2, 2);
        n2 += __shfl_xor_sync(0xffffffffu, n2, 4);
        n2 += __shfl_xor_sync(0xffffffffu, n2, 8);
        n2 += __shfl_xor_sync(0xffffffffu, n2, 16);
        float nrm = sqrtf(n2);
        float scale = n2 / ((1.f + n2) * (nrm + 1e-8f));
        s_v[t] = x * scale;
    }
    __syncthreads();

    const float4 v0 = *(const float4*)&s_v[8 * l];
    const float4 v1 = *(const float4*)&s_v[8 * l + 4];

    float acc[8];
    #pragma unroll
    for (int i = 0; i < 8; ++i) acc[i] = 0.f;

    #pragma unroll
    for (int s = 0; s < 4; ++s) {
        const uint4 xa = A[2 * s], xb = A[2 * s + 1];
        float fx[8], fy[8];
        {
            float2 f;
            f = __half22float2(*(const __half2*)&xa.x); fx[0]=f.x; fx[1]=f.y;
            f = __half22float2(*(const __half2*)&xa.y); fx[2]=f.x; fx[3]=f.y;
            f = __half22float2(*(const __half2*)&xa.z); fx[4]=f.x; fx[5]=f.y;
            f = __half22float2(*(const __half2*)&xa.w); fx[6]=f.x; fx[7]=f.y;
            f = __half22float2(*(const __half2*)&xb.x); fy[0]=f.x; fy[1]=f.y;
            f = __half22float2(*(const __half2*)&xb.y); fy[2]=f.x; fy[3]=f.y;
            f = __half22float2(*(const __half2*)&xb.z); fy[4]=f.x; fy[5]=f.y;
            f = __half22float2(*(const __half2*)&xb.w); fy[6]=f.x; fy[7]=f.y;
        }
        float d0 = fx[0]*v0.x + fx[1]*v0.y + fx[2]*v0.z + fx[3]*v0.w
                 + fx[4]*v1.x + fx[5]*v1.y + fx[6]*v1.z + fx[7]*v1.w;
        float d1 = fy[0]*v0.x + fy[1]*v0.y + fy[2]*v0.z + fy[3]*v0.w
                 + fy[4]*v1.x + fy[5]*v1.y + fy[6]*v1.z + fy[7]*v1.w;
        d0 += __shfl_xor_sync(0xffffffffu, d0, 1);
        d1 += __shfl_xor_sync(0xffffffffu, d1, 1);
        d0 += __shfl_xor_sync(0xffffffffu, d0, 2);
        d1 += __shfl_xor_sync(0xffffffffu, d1, 2);
        float bn0 = d0, bn1 = d1;
        if (ITER == 2) { bn0 += bpre[2 * s]; bn1 += bpre[2 * s + 1]; }
        else if ((l & 3) == 0) {
            bbp[(2 * s) * EE + e]     = bn0;   // b1 = uv0 (b starts at 0)
            bbp[(2 * s + 1) * EE + e] = bn1;
        }

        // softmax over E (butterfly spans the 8 e-lanes; og lanes identical)
        float m0 = bn0, m1 = bn1;
        m0 = fmaxf(m0, __shfl_xor_sync(0xffffffffu, m0, 4));
        m1 = fmaxf(m1, __shfl_xor_sync(0xffffffffu, m1, 4));
        m0 = fmaxf(m0, __shfl_xor_sync(0xffffffffu, m0, 8));
        m1 = fmaxf(m1, __shfl_xor_sync(0xffffffffu, m1, 8));
        m0 = fmaxf(m0, __shfl_xor_sync(0xffffffffu, m0, 16));
        m1 = fmaxf(m1, __shfl_xor_sync(0xffffffffu, m1, 16));
        float ex0 = __expf(bn0 - m0);
        float ex1 = __expf(bn1 - m1);
        float sm0 = ex0, sm1 = ex1;
        sm0 += __shfl_xor_sync(0xffffffffu, sm0, 4);
        sm1 += __shfl_xor_sync(0xffffffffu, sm1, 4);
        sm0 += __shfl_xor_sync(0xffffffffu, sm0, 8);
        sm1 += __shfl_xor_sync(0xffffffffu, sm1, 8);
        sm0 += __shfl_xor_sync(0xffffffffu, sm0, 16);
        sm1 += __shfl_xor_sync(0xffffffffu, sm1, 16);
        const float c0 = __fdividef(ex0, sm0);
        const float c1 = __fdividef(ex1, sm1);

        #pragma unroll
        for (int i = 0; i < 8; ++i) acc[i] += c0 * fx[i] + c1 * fy[i];
    }

    // per-warp slice (disjoint within warp -> deterministic)
    float* sw = &s_sh[w * EO + 8 * l];
    #pragma unroll
    for (int i = 0; i < 8; ++i) sw[i] = acc[i];
    __syncthreads();
    float sum = 0.f;
    #pragma unroll
    for (int ww = 0; ww < 8; ++ww) sum += s_sh[ww * EO + t];
    g_spart[chunk * (BB * EO) + b * EO + t] = sum;
}

// ---------------------------------------------------------------------------
// Launch
// ---------------------------------------------------------------------------
extern "C" void kernel_launch(void* const* d_in, const int* in_sizes, int n_in,
                              void* d_out, int out_size) {
    const float* u = (const float*)d_in[0];
    const float* W = (const float*)d_in[1];
    if (n_in >= 2 && in_sizes[0] > in_sizes[1]) {  // u = 4.19M elems, W = 16.78M
        const float* tmp = u; u = W; W = tmp;
    }
    float* out = (float*)d_out;
    (void)out_size;

    cudaFuncSetAttribute(gemm_kernel,
                         cudaFuncAttributeMaxDynamicSharedMemorySize,
                         GEMM_SMEM_BYTES);

    gemm_kernel<<<NN, 256, GEMM_SMEM_BYTES>>>(u, W);   // u_hat (fp16)
    reduce_s0_kernel<<<BB * CH, 256>>>();              // s0 partials (c=1/8)
    routing_kernel<1><<<BB * CH, 256>>>();             // v0 prologue, b1, s1
    routing_kernel<2><<<BB * CH, 256>>>();             // v1 prologue, b2, s2
    squash_final_kernel<<<64, 256>>>(out);             // v2 -> d_out
}

// round 9
// speedup vs baseline: 1.4120x; 1.0008x over previous
#include <cuda_runtime.h>
#include <cuda_fp16.h>
#include <cstdint>

// Problem dims (fixed by reference setup_inputs)
#define BB   64
#define NN   1024
#define EE   8
#define OO   32
#define II   64
#define EO   256
#define NEO  (NN*EO)
#define CH   16

// ---------------------------------------------------------------------------
// Scratch (device globals; no allocation allowed)
// ---------------------------------------------------------------------------
__device__ __half g_u_hat[(size_t)BB * NN * EO];   // 32 MB [b][n][eo]
__device__ float  g_spart[CH * BB * EO];           // 1 MB  [chunk][b][eo]
__device__ float  g_b[BB * NN * EE];               // logits [b][n][e]

// ---------------------------------------------------------------------------
// PTX helpers (sm_90-level features only; tcgen05 is rejected by this
// harness's compute_103 PTX target)
// ---------------------------------------------------------------------------
__device__ __forceinline__ uint32_t smem_u32(const void* p) {
    uint32_t a;
    asm("{ .reg .u64 t; cvta.to.shared.u64 t, %1; cvt.u32.u64 %0, t; }"
        : "=r"(a) : "l"(p));
    return a;
}
#define MBAR_INIT(a, c) \
    asm volatile("mbarrier.init.shared.b64 [%0], %1;" :: "r"(a), "r"(c) : "memory")
#define MBAR_EXPECT(a, bytes) \
    asm volatile("mbarrier.arrive.expect_tx.shared.b64 _, [%0], %1;" \
                 :: "r"(a), "r"(bytes) : "memory")
#define BULK_G2S(dst, src, bytes, mbar) \
    asm volatile("cp.async.bulk.shared::cta.global.mbarrier::complete_tx::bytes " \
                 "[%0], [%1], %2, [%3];" \
                 :: "r"(dst), "l"(src), "r"(bytes), "r"(mbar) : "memory")
#define MBAR_WAIT(mbar, ph) do { \
    asm volatile("{\n\t.reg .pred P1;\n\tWL_%=:\n\t" \
        "mbarrier.try_wait.parity.acquire.cta.shared::cta.b64 P1, [%0], %1, 0x989680;\n\t" \
        "@P1 bra.uni WD_%=;\n\tbra.uni WL_%=;\n\tWD_%=:\n\t}" \
        :: "r"((uint32_t)(mbar)), "r"((uint32_t)(ph)) : "memory"); } while (0)

// fp32x2 packed FMA (PTX-only; ptxas never auto-fuses FFMA2)
__device__ __forceinline__ void ffma2(unsigned long long& d,
                                      unsigned long long a,
                                      unsigned long long b) {
    asm("fma.rn.f32x2 %0, %1, %2, %0;" : "+l"(d) : "l"(a), "l"(b));
}
__device__ __forceinline__ float2 asf2(unsigned long long v) {
    union { unsigned long long u; float2 f; } c; c.u = v; return c.f;
}
// pack two floats into f16x2 with `lo` in the low half (memory-first elem)
__device__ __forceinline__ unsigned pack_f16(float lo, float hi) {
    unsigned r;
    asm("cvt.rn.f16x2.f32 %0, %1, %2;" : "=r"(r) : "f"(hi), "f"(lo));
    return r;
}

// ---------------------------------------------------------------------------
// Kernel 1: u_hat[b,n,eo] = sum_i W[n,eo,i] * u[b,n,i]   (fp16 output)
// Proven round-6 FFMA2 kernel: one CTA per n, 256 threads.
// sW: [k][eo ^ ((k>>2 & 7)<<2)] swizzle; sUd: duplicated {u,u} pairs.
// Lane l owns eo {4l..4l+3, 4l+128..4l+131}; warp w owns b {8w..8w+7}.
// ---------------------------------------------------------------------------
#define SW_FLOATS  (64*256)
#define SUD_FLOATS (64*128)
#define GEMM_SMEM_BYTES ((SW_FLOATS + SUD_FLOATS) * 4)

__global__ __launch_bounds__(256, 2)
void gemm_kernel(const float* __restrict__ u, const float* __restrict__ W) {
    extern __shared__ float smem[];
    float* sW  = smem;                 // [64][256] swizzled
    float* sUd = smem + SW_FLOATS;     // [64][128] dup'd

    const int n = blockIdx.x;
    const int t = threadIdx.x;
    const int w = t >> 5;
    const int l = t & 31;

    // ---- fill sW: coalesced float4 LDG, swizzled scatter STS (<=2-way)
    {
        const float4* wg4 = (const float4*)(W + (size_t)n * (EO * II));
        #pragma unroll
        for (int it = 0; it < 16; ++it) {
            int idx = t + it * 256;          // 0..4095 float4s
            int eo  = idx >> 4;
            int kf4 = idx & 15;
            float4 v = wg4[idx];
            int col  = eo ^ ((kf4 & 7) << 2);
            float* p = &sW[(kf4 * 4) * 256 + col];
            p[0]   = v.x;
            p[256] = v.y;
            p[512] = v.z;
            p[768] = v.w;
        }
    }
    // ---- fill sUd: duplicated pairs {u,u} -> FFMA2 B-operand loads directly
    {
        const int b  = t >> 2;
        const int fq = t & 3;
        const float4* ug4 = (const float4*)(u + ((size_t)b * NN + n) * II);
        float2* sUd2 = (float2*)sUd;     // [64][64] in float2 units
        #pragma unroll
        for (int i = 0; i < 4; ++i) {
            int f = fq * 4 + i;
            float4 v = ug4[f];
            int k0 = f * 4;
            sUd2[(k0 + 0) * 64 + b] = make_float2(v.x, v.x);
            sUd2[(k0 + 1) * 64 + b] = make_float2(v.y, v.y);
            sUd2[(k0 + 2) * 64 + b] = make_float2(v.z, v.z);
            sUd2[(k0 + 3) * 64 + b] = make_float2(v.w, v.w);
        }
    }
    __syncthreads();

    unsigned long long acc[8][4];
    #pragma unroll
    for (int r = 0; r < 8; ++r)
        #pragma unroll
        for (int p = 0; p < 4; ++p) acc[r][p] = 0ULL;

    const float* ubase = &sUd[w * 16];

    #pragma unroll 4
    for (int k4 = 0; k4 < 16; ++k4) {
        const int X4 = (k4 & 7) << 2;
        const float* wbase = &sW[(4 * l) ^ X4];
        #pragma unroll
        for (int j = 0; j < 4; ++j) {
            const int k = k4 * 4 + j;
            const ulonglong2 w0 = *(const ulonglong2*)&wbase[k * 256];
            const ulonglong2 w1 = *(const ulonglong2*)&wbase[k * 256 + 128];
            const ulonglong2* ub = (const ulonglong2*)&ubase[k * 128];
            const ulonglong2 u0 = ub[0], u1 = ub[1], u2 = ub[2], u3 = ub[3];

            ffma2(acc[0][0], u0.x, w0.x); ffma2(acc[0][1], u0.x, w0.y);
            ffma2(acc[0][2], u0.x, w1.x); ffma2(acc[0][3], u0.x, w1.y);
            ffma2(acc[1][0], u0.y, w0.x); ffma2(acc[1][1], u0.y, w0.y);
            ffma2(acc[1][2], u0.y, w1.x); ffma2(acc[1][3], u0.y, w1.y);
            ffma2(acc[2][0], u1.x, w0.x); ffma2(acc[2][1], u1.x, w0.y);
            ffma2(acc[2][2], u1.x, w1.x); ffma2(acc[2][3], u1.x, w1.y);
            ffma2(acc[3][0], u1.y, w0.x); ffma2(acc[3][1], u1.y, w0.y);
            ffma2(acc[3][2], u1.y, w1.x); ffma2(acc[3][3], u1.y, w1.y);
            ffma2(acc[4][0], u2.x, w0.x); ffma2(acc[4][1], u2.x, w0.y);
            ffma2(acc[4][2], u2.x, w1.x); ffma2(acc[4][3], u2.x, w1.y);
            ffma2(acc[5][0], u2.y, w0.x); ffma2(acc[5][1], u2.y, w0.y);
            ffma2(acc[5][2], u2.y, w1.x); ffma2(acc[5][3], u2.y, w1.y);
            ffma2(acc[6][0], u3.x, w0.x); ffma2(acc[6][1], u3.x, w0.y);
            ffma2(acc[6][2], u3.x, w1.x); ffma2(acc[6][3], u3.x, w1.y);
            ffma2(acc[7][0], u3.y, w0.x); ffma2(acc[7][1], u3.y, w0.y);
            ffma2(acc[7][2], u3.y, w1.x); ffma2(acc[7][3], u3.y, w1.y);
        }
    }

    // ---- epilogue: fp16 stores; lane writes eo 4l..4l+3 and +128, coalesced
    __half* outp = g_u_hat + (size_t)n * EO + 4 * l;
    #pragma unroll
    for (int r = 0; r < 8; ++r) {
        float2 p0 = asf2(acc[r][0]), p1 = asf2(acc[r][1]);
        float2 p2 = asf2(acc[r][2]), p3 = asf2(acc[r][3]);
        __half* pp = outp + (size_t)(w * 8 + r) * NEO;
        uint2 lo, hi;
        lo.x = pack_f16(p0.x, p0.y); lo.y = pack_f16(p1.x, p1.y);
        hi.x = pack_f16(p2.x, p2.y); hi.y = pack_f16(p3.x, p3.y);
        *(uint2*)pp         = lo;
        *(uint2*)(pp + 128) = hi;
    }
}

// ---------------------------------------------------------------------------
// Kernel 2: s0 partial = (1/8)*sum_n u_hat via TMA bulk staging.
// grid 1024 = 64 b x 16 chunks (64 n each, 32 KB contiguous tile).
// ---------------------------------------------------------------------------
__global__ __launch_bounds__(256)
void reduce_s0_kernel() {
    __shared__ __align__(128) char s_tile[64 * 512];   // 32 KB
    __shared__ float s_sh[8 * EO];
    __shared__ __align__(8) uint64_t s_mbar;
    const int b = blockIdx.x >> 4;
    const int chunk = blockIdx.x & 15;
    const int t = threadIdx.x, w = t >> 5, l = t & 31;
    const uint32_t mbar = smem_u32(&s_mbar);

    if (t == 0) MBAR_INIT(mbar, 1);
    __syncthreads();
    if (t == 0) {
        const __half* gp = g_u_hat + (size_t)b * NEO + (size_t)(chunk * 64) * EO;
        uint64_t ga = (uint64_t)__cvta_generic_to_global((void*)gp);
        MBAR_EXPECT(mbar, 32768);
        BULK_G2S(smem_u32(s_tile), ga, 32768, mbar);
    }
    MBAR_WAIT(mbar, 0);

    float acc[8];
    #pragma unroll
    for (int i = 0; i < 8; ++i) acc[i] = 0.f;
    #pragma unroll
    for (int j = 0; j < 8; ++j) {
        uint4 r = *(const uint4*)(s_tile + (w * 8 + j) * 512 + l * 16);
        float2 f;
        f = __half22float2(*(const __half2*)&r.x); acc[0] += f.x; acc[1] += f.y;
        f = __half22float2(*(const __half2*)&r.y); acc[2] += f.x; acc[3] += f.y;
        f = __half22float2(*(const __half2*)&r.z); acc[4] += f.x; acc[5] += f.y;
        f = __half22float2(*(const __half2*)&r.w); acc[6] += f.x; acc[7] += f.y;
    }
    float* sw = &s_sh[w * EO + 8 * l];
    #pragma unroll
    for (int i = 0; i < 8; ++i) sw[i] = acc[i];
    __syncthreads();
    float sum = 0.f;
    #pragma unroll
    for (int ww = 0; ww < 8; ++ww) sum += s_sh[ww * EO + t];
    g_spart[chunk * (BB * EO) + b * EO + t] = sum * 0.125f;
}

// ---------------------------------------------------------------------------
// Kernel 3 (final): squash partial sums -> d_out
// ---------------------------------------------------------------------------
__global__ __launch_bounds__(256)
void squash_final_kernel(float* __restrict__ out) {
    const int t = threadIdx.x, w = t >> 5, l = t & 31;
    const int idx = (blockIdx.x * 8 + w) * 32 + l;
    float x = 0.f;
    #pragma unroll
    for (int c = 0; c < CH; ++c) x += g_spart[c * (BB * EO) + idx];
    float n2 = x * x;
    n2 += __shfl_xor_sync(0xffffffffu, n2, 1);
    n2 += __shfl_xor_sync(0xffffffffu, n2, 2);
    n2 += __shfl_xor_sync(0xffffffffu, n2, 4);
    n2 += __shfl_xor_sync(0xffffffffu, n2, 8);
    n2 += __shfl_xor_sync(0xffffffffu, n2, 16);
    float nrm = sqrtf(n2);
    float scale = n2 / ((1.f + n2) * (nrm + 1e-8f));
    out[idx] = x * scale;
}

// ---------------------------------------------------------------------------
// Kernel 4/5: fused routing iteration with TMA bulk staging.
// grid 1024 = 64 b x 16 chunks. Squash prologue + logit loads overlap TMA.
// ---------------------------------------------------------------------------
template <int ITER>
__global__ __launch_bounds__(256)
void routing_kernel() {
    __shared__ __align__(128) char s_tile[64 * 512];   // 32 KB
    __shared__ float s_v[EO];
    __shared__ float s_sh[8 * EO];
    __shared__ __align__(8) uint64_t s_mbar;
    const int b = blockIdx.x >> 4;
    const int chunk = blockIdx.x & 15;
    const int t = threadIdx.x, w = t >> 5, l = t & 31;
    const int e = l >> 2;
    const uint32_t mbar = smem_u32(&s_mbar);

    if (t == 0) MBAR_INIT(mbar, 1);
    __syncthreads();
    if (t == 0) {
        const __half* gp = g_u_hat + (size_t)b * NEO + (size_t)(chunk * 64) * EO;
        uint64_t ga = (uint64_t)__cvta_generic_to_global((void*)gp);
        MBAR_EXPECT(mbar, 32768);
        BULK_G2S(smem_u32(s_tile), ga, 32768, mbar);
    }

    const int n0 = chunk * 64 + w * 8;
    float* bbp = g_b + b * (NN * EE) + n0 * EE;
    float bpre[8];
    if (ITER == 2) {
        #pragma unroll
        for (int nn = 0; nn < 8; ++nn) bpre[nn] = bbp[nn * EE + e];
    }

    // prologue: v = squash(sum_c spart) — overlaps the TMA
    {
        float x = 0.f;
        #pragma unroll
        for (int c = 0; c < CH; ++c) x += g_spart[c * (BB * EO) + b * EO + t];
        float n2 = x * x;
        n2 += __shfl_xor_sync(0xffffffffu, n2, 1);
        n2 += __shfl_xor_sync(0xffffffffu, n2, 2);
        n2 += __shfl_xor_sync(0xffffffffu, n2, 4);
        n2 += __shfl_xor_sync(0xffffffffu, n2, 8);
        n2 += __shfl_xor_sync(0xffffffffu, n2, 16);
        float nrm = sqrtf(n2);
        float scale = n2 / ((1.f + n2) * (nrm + 1e-8f));
        s_v[t] = x * scale;
    }
    __syncthreads();

    const float4 v0 = *(const float4*)&s_v[8 * l];
    const float4 v1 = *(const float4*)&s_v[8 * l + 4];

    MBAR_WAIT(mbar, 0);

    float acc[8];
    #pragma unroll
    for (int i = 0; i < 8; ++i) acc[i] = 0.f;

    const char* base = s_tile + (w * 8) * 512 + l * 16;

    #pragma unroll
    for (int s = 0; s < 4; ++s) {
        const uint4 xa = *(const uint4*)(base + (2 * s) * 512);
        const uint4 xb = *(const uint4*)(base + (2 * s + 1) * 512);
        float fx[8], fy[8];
        {
            float2 f;
            f = __half22float2(*(const __half2*)&xa.x); fx[0]=f.x; fx[1]=f.y;
            f = __half22float2(*(const __half2*)&xa.y); fx[2]=f.x; fx[3]=f.y;
            f = __half22float2(*(const __half2*)&xa.z); fx[4]=f.x; fx[5]=f.y;
            f = __half22float2(*(const __half2*)&xa.w); fx[6]=f.x; fx[7]=f.y;
            f = __half22float2(*(const __half2*)&xb.x); fy[0]=f.x; fy[1]=f.y;
            f = __half22float2(*(const __half2*)&xb.y); fy[2]=f.x; fy[3]=f.y;
            f = __half22float2(*(const __half2*)&xb.z); fy[4]=f.x; fy[5]=f.y;
            f = __half22float2(*(const __half2*)&xb.w); fy[6]=f.x; fy[7]=f.y;
        }
        float d0 = fx[0]*v0.x + fx[1]*v0.y + fx[2]*v0.z + fx[3]*v0.w
                 + fx[4]*v1.x + fx[5]*v1.y + fx[6]*v1.z + fx[7]*v1.w;
        float d1 = fy[0]*v0.x + fy[1]*v0.y + fy[2]*v0.z + fy[3]*v0.w
                 + fy[4]*v1.x + fy[5]*v1.y + fy[6]*v1.z + fy[7]*v1.w;
        d0 += __shfl_xor_sync(0xffffffffu, d0, 1);
        d1 += __shfl_xor_sync(0xffffffffu, d1, 1);
        d0 += __shfl_xor_sync(0xffffffffu, d0, 2);
        d1 += __shfl_xor_sync(0xffffffffu, d1, 2);
        float bn0 = d0, bn1 = d1;
        if (ITER == 2) { bn0 += bpre[2 * s]; bn1 += bpre[2 * s + 1]; }
        else if ((l & 3) == 0) {
            bbp[(2 * s) * EE + e]     = bn0;   // b1 = uv0 (b starts at 0)
            bbp[(2 * s + 1) * EE + e] = bn1;
        }

        float m0 = bn0, m1 = bn1;
        m0 = fmaxf(m0, __shfl_xor_sync(0xffffffffu, m0, 4));
        m1 = fmaxf(m1, __shfl_xor_sync(0xffffffffu, m1, 4));
        m0 = fmaxf(m0, __shfl_xor_sync(0xffffffffu, m0, 8));
        m1 = fmaxf(m1, __shfl_xor_sync(0xffffffffu, m1, 8));
        m0 = fmaxf(m0, __shfl_xor_sync(0xffffffffu, m0, 16));
        m1 = fmaxf(m1, __shfl_xor_sync(0xffffffffu, m1, 16));
        float ex0 = __expf(bn0 - m0);
        float ex1 = __expf(bn1 - m1);
        float sm0 = ex0, sm1 = ex1;
        sm0 += __shfl_xor_sync(0xffffffffu, sm0, 4);
        sm1 += __shfl_xor_sync(0xffffffffu, sm1, 4);
        sm0 += __shfl_xor_sync(0xffffffffu, sm0, 8);
        sm1 += __shfl_xor_sync(0xffffffffu, sm1, 8);
        sm0 += __shfl_xor_sync(0xffffffffu, sm0, 16);
        sm1 += __shfl_xor_sync(0xffffffffu, sm1, 16);
        const float c0 = __fdividef(ex0, sm0);
        const float c1 = __fdividef(ex1, sm1);

        #pragma unroll
        for (int i = 0; i < 8; ++i) acc[i] += c0 * fx[i] + c1 * fy[i];
    }

    float* sw = &s_sh[w * EO + 8 * l];
    #pragma unroll
    for (int i = 0; i < 8; ++i) sw[i] = acc[i];
    __syncthreads();
    float sum = 0.f;
    #pragma unroll
    for (int ww = 0; ww < 8; ++ww) sum += s_sh[ww * EO + t];
    g_spart[chunk * (BB * EO) + b * EO + t] = sum;
}

// ---------------------------------------------------------------------------
// Launch
// ---------------------------------------------------------------------------
extern "C" void kernel_launch(void* const* d_in, const int* in_sizes, int n_in,
                              void* d_out, int out_size) {
    const float* u = (const float*)d_in[0];
    const float* W = (const float*)d_in[1];
    if (n_in >= 2 && in_sizes[0] > in_sizes[1]) {  // u = 4.19M elems, W = 16.78M
        const float* tmp = u; u = W; W = tmp;
    }
    float* out = (float*)d_out;
    (void)out_size;

    cudaFuncSetAttribute(gemm_kernel,
                         cudaFuncAttributeMaxDynamicSharedMemorySize,
                         GEMM_SMEM_BYTES);

    gemm_kernel<<<NN, 256, GEMM_SMEM_BYTES>>>(u, W);   // u_hat (fp16)
    reduce_s0_kernel<<<BB * CH, 256>>>();              // s0 partials (c=1/8)
    routing_kernel<1><<<BB * CH, 256>>>();             // v0 prologue, b1, s1
    routing_kernel<2><<<BB * CH, 256>>>();             // v1 prologue, b2, s2
    squash_final_kernel<<<64, 256>>>(out);             // v2 -> d_out
}